// round 16
// baseline (speedup 1.0000x reference)
#include <cuda_runtime.h>
#include <cuda_bf16.h>
#include <math.h>
#include <stdint.h>

// ---------------- problem constants ----------------
#define EMB    300
#define SEQ    100
#define KW     5
#define KN     50
#define KMAX   3
#define MLP1   75
#define LP     (SEQ - KW + 1)   // 96
#define KC     64               // K per chunk
#define NCHK   5                // 5*64=320 >= 300; last chunk 3 ks
#define BT     176              // tensor B rows (cols 0..175)
#define MROWS  112

// ---------------- device scratch ----------------
__device__ float g_cv[EMB];
__device__ float g_gate[KN];
__device__ float g_bias[KN];
// bf16-split B for tensor path: [c][hi|lo][n' 0..255][k 0..63] (full 256 kept; main stages rows<176)
__device__ __align__(16) unsigned short g_bimg[NCHK * 2 * 256 * KC];
// fp32 folded W for hybrid fp32 path: [kp 0..149][j 0..79] float2 (cols n'=176+j)
__device__ __align__(16) float g_wf32[150 * 80 * 2];

// ---------------- helpers ----------------
__device__ __forceinline__ unsigned short f2bf(float x) {
    unsigned u = __float_as_uint(x);
    return (unsigned short)((u + 0x7FFFu + ((u >> 16) & 1u)) >> 16);
}
__device__ __forceinline__ float bf2f(unsigned short h) {
    return __uint_as_float(((unsigned)h) << 16);
}
__device__ __forceinline__ uint32_t smem_u32(const void* p) {
    uint32_t a;
    asm("{ .reg .u64 t; cvta.to.shared.u64 t, %1; cvt.u32.u64 %0, t; }" : "=r"(a) : "l"(p));
    return a;
}
__device__ __forceinline__ void ldsm_x4(uint32_t* r, uint32_t addr) {
    asm volatile("ldmatrix.sync.aligned.m8n8.x4.shared.b16 {%0,%1,%2,%3}, [%4];"
                 : "=r"(r[0]), "=r"(r[1]), "=r"(r[2]), "=r"(r[3]) : "r"(addr));
}
__device__ __forceinline__ void ldsm_x2(uint32_t* r, uint32_t addr) {
    asm volatile("ldmatrix.sync.aligned.m8n8.x2.shared.b16 {%0,%1}, [%2];"
                 : "=r"(r[0]), "=r"(r[1]) : "r"(addr));
}
__device__ __forceinline__ void mma_bf16(float* d, const uint32_t* a, const uint32_t* b) {
    asm volatile("mma.sync.aligned.m16n8k16.row.col.f32.bf16.bf16.f32 "
                 "{%0,%1,%2,%3}, {%4,%5,%6,%7}, {%8,%9}, {%0,%1,%2,%3};"
                 : "+f"(d[0]), "+f"(d[1]), "+f"(d[2]), "+f"(d[3])
                 : "r"(a[0]), "r"(a[1]), "r"(a[2]), "r"(a[3]), "r"(b[0]), "r"(b[1]));
}

// ---------------- prepA ----------------
__global__ void dazer_prepA(const int* __restrict__ q, const float* __restrict__ emb) {
    int t = threadIdx.x;
    if (t < EMB) {
        float s = 0.f;
        #pragma unroll
        for (int k = 0; k < 5; k++) s += emb[(size_t)q[k] * EMB + t];
        g_cv[t] = s * 0.2f;
    }
}

// ---------------- prepB ----------------
__global__ void dazer_prepB(const float* __restrict__ conv_w,
                            const float* __restrict__ conv_b,
                            const float* __restrict__ gate_w,
                            const float* __restrict__ gate_b) {
    __shared__ float red[256];
    __shared__ float cvs[EMB];
    const int tid = threadIdx.x;
    const int bid = blockIdx.x;

    for (int e = tid; e < EMB; e += 256) cvs[e] = g_cv[e];
    __syncthreads();

    if (bid < KN) {
        const int n = bid;
        float s = 0.f;
        for (int e = tid; e < EMB; e += 256) s += cvs[e] * gate_w[e * KN + n];
        red[tid] = s; __syncthreads();
        for (int o = 128; o; o >>= 1) { if (tid < o) red[tid] += red[tid + o]; __syncthreads(); }
        if (tid == 0) g_gate[n] = 1.f / (1.f + expf(-(red[0] + gate_b[n])));
        __syncthreads();
        float bs = 0.f;
        for (int idx = tid; idx < KW * EMB; idx += 256) {
            int w = idx / EMB, e = idx - w * EMB;
            bs += cvs[e] * conv_w[(w * (3 * EMB) + 2 * EMB + e) * KN + n];
        }
        red[tid] = bs; __syncthreads();
        for (int o = 128; o; o >>= 1) { if (tid < o) red[tid] += red[tid + o]; __syncthreads(); }
        if (tid == 0) g_bias[n] = red[0] + conv_b[n];
    } else {
        // bf16-split images for tensor cols (only rows < BT are consumed, fill all)
        const int total = NCHK * 256 * KC;
        for (int idx = (bid - KN) * 256 + tid; idx < total; idx += 100 * 256) {
            int k = idx & 63;
            int r = (idx >> 6) & 255;
            int c = idx >> 14;
            float v = 0.f;
            if (r < KW * KN) {
                int w = r / KN, n = r - w * KN;
                int e = c * KC + k;
                if (e < EMB) {
                    int base = w * (3 * EMB);
                    v = conv_w[(base + e) * KN + n]
                      + cvs[e] * conv_w[(base + EMB + e) * KN + n]
                      -          conv_w[(base + 2 * EMB + e) * KN + n];
                }
            }
            unsigned short hi = f2bf(v);
            unsigned short lo = f2bf(v - bf2f(hi));
            g_bimg[((c * 2 + 0) * 256 + r) * KC + k] = hi;
            g_bimg[((c * 2 + 1) * 256 + r) * KC + k] = lo;
        }
        // fp32 folded W for cols 176..255: g_wf32[(kp*80+j)*2 + {0,1}]
        const int tot2 = 150 * 80;
        for (int idx = (bid - KN) * 256 + tid; idx < tot2; idx += 100 * 256) {
            int j  = idx % 80;
            int kp = idx / 80;
            int np = 176 + j;
            float v0 = 0.f, v1 = 0.f;
            if (np < KW * KN) {
                int w = np / KN, n = np - w * KN;
                int e0 = 2 * kp;
                int base = w * (3 * EMB);
                v0 = conv_w[(base + e0) * KN + n]
                   + cvs[e0] * conv_w[(base + EMB + e0) * KN + n]
                   -           conv_w[(base + 2 * EMB + e0) * KN + n];
                int e1 = e0 + 1;
                v1 = conv_w[(base + e1) * KN + n]
                   + cvs[e1] * conv_w[(base + EMB + e1) * KN + n]
                   -           conv_w[(base + 2 * EMB + e1) * KN + n];
            }
            g_wf32[idx * 2]     = v0;
            g_wf32[idx * 2 + 1] = v1;
        }
    }
}

// ---------------- main: 704 thr = 14 tensor warps + 8 fp32 warps ----------
#define O_EHI  0
#define O_ELO  16128                     // 112*144
#define O_BHI  32256
#define O_BLO  (32256 + BT * 144)        // 57600
#define BUFSZ  (57600 + BT * 144)        // 82944
#define BUF0   2048
#define BUF1   (BUF0 + BUFSZ)            // 84992
#define DSM_OFF BUF1                     // Dsm aliases BUF1 (last gemm uses BUF0)
#define DSTRIDE 264
#define SMEM_BYTES (DSM_OFF + SEQ * DSTRIDE * 4)   // 190592

__global__ __launch_bounds__(704, 1)
void dazer_main(const int* __restrict__ input_d,
                const float* __restrict__ emb,
                const float* __restrict__ hid_w,
                const float* __restrict__ hid_b,
                const float* __restrict__ score_w,
                const float* __restrict__ score_b,
                float* __restrict__ out, int Btot) {
    extern __shared__ char smc[];
    int*   docids = (int*)smc;                    // [104]
    float* enc    = (float*)(smc + 448);          // [152]
    float* mlp1s  = (float*)(smc + 1088);         // [76]
    float* Dsm    = (float*)(smc + DSM_OFF);      // [100][264]

    const int tid  = threadIdx.x;
    const int lane = tid & 31;
    const int wid  = tid >> 5;        // 0..21
    const int b    = blockIdx.x;
    const bool isT = (wid < 14);
    const int mt   = wid >> 1;        // tensor: 0..6
    const int nh   = wid & 1;         // tensor: 0..1

    if (tid < SEQ) docids[tid] = input_d[b * SEQ + tid];
    __syncthreads();

    const uint32_t sb = smem_u32(smc);
    const uint32_t brow = (uint32_t)((lane & 7) + ((lane & 16) >> 1));

    // ---- fp32-warp identity ----
    const int ft = tid - 448;                       // 0..255 for fp32 warps
    const int cg = ft & 15;                         // 5-col group
    const int rg = ft >> 4;                         // 0..15 -> rows 7rg..7rg+6
    const float* erow[7];
    if (!isT) {
        #pragma unroll
        for (int i = 0; i < 7; i++) {
            int r = 7 * rg + i;
            erow[i] = emb + (size_t)docids[r < SEQ ? r : 0] * EMB;
        }
    }

    // ---- staging lambdas (all 704 threads) ----
    float2 ev[6];
    auto stageE_load = [&](int c) {
        #pragma unroll
        for (int i = 0; i < 6; i++) {
            int idx = i * 704 + tid;               // 3584 = 112 * 32
            float2 v = make_float2(0.f, 0.f);
            if (idx < MROWS * 32) {
                int row = idx >> 5, kp = idx & 31;
                int e0  = c * KC + kp * 2;
                if (row < SEQ) {
                    const float* er = emb + (size_t)docids[row] * EMB;
                    if (e0 < EMB)     v.x = er[e0];
                    if (e0 + 1 < EMB) v.y = er[e0 + 1];
                }
            }
            ev[i] = v;
        }
    };
    auto stageE_store = [&](int base) {
        #pragma unroll
        for (int i = 0; i < 6; i++) {
            int idx = i * 704 + tid;
            if (idx < MROWS * 32) {
                int row = idx >> 5, kp = idx & 31;
                unsigned short h0 = f2bf(ev[i].x), h1 = f2bf(ev[i].y);
                unsigned short l0 = f2bf(ev[i].x - bf2f(h0));
                unsigned short l1 = f2bf(ev[i].y - bf2f(h1));
                *(uint32_t*)(smc + base + O_EHI + row * 144 + kp * 4) =
                    (uint32_t)h0 | ((uint32_t)h1 << 16);
                *(uint32_t*)(smc + base + O_ELO + row * 144 + kp * 4) =
                    (uint32_t)l0 | ((uint32_t)l1 << 16);
            }
        }
    };
    auto stageB = [&](int c, int base) {            // rows 0..BT-1 only
        const char* bsrc = (const char*)g_bimg;
        #pragma unroll
        for (int img = 0; img < 2; img++) {
            int dsto = base + (img ? O_BLO : O_BHI);
            #pragma unroll
            for (int i = 0; i < 2; i++) {
                int idx = i * 704 + tid;            // BT*8 = 1408
                if (idx < BT * 8) {
                    int row = idx >> 3, u = idx & 7;
                    uint32_t dst = sb + (uint32_t)(dsto + row * 144 + u * 16);
                    const void* src = bsrc +
                        ((size_t)((c * 2 + img) * 256 + row) * KC) * 2 + u * 16;
                    asm volatile("cp.async.cg.shared.global [%0], [%1], 16;"
                                 :: "r"(dst), "l"(src));
                }
            }
        }
        asm volatile("cp.async.commit_group;" ::: "memory");
    };

    // ---- prologue: chunk 0 into BUF0 ----
    stageB(0, BUF0);
    stageE_load(0);
    stageE_store(BUF0);
    asm volatile("cp.async.wait_group 0;" ::: "memory");
    __syncthreads();

    float acc[44];                                   // tensor: 11 n8-tiles
    float facc[7][5];                                // fp32: 7 rows x 5 cols
    #pragma unroll
    for (int i = 0; i < 44; i++) acc[i] = 0.f;
    #pragma unroll
    for (int i = 0; i < 7; i++)
        #pragma unroll
        for (int j = 0; j < 5; j++) facc[i][j] = 0.f;

    #pragma unroll 1
    for (int c = 0; c < NCHK; c++) {
        const int eb = (c & 1) ? BUF1 : BUF0;
        const int ob = (c & 1) ? BUF0 : BUF1;
        if (c + 1 < NCHK) {
            stageB(c + 1, ob);
            stageE_load(c + 1);
        }

        if (isT) {
            // ---- tensor warps: D[16, 88] += E[16,64]*B[88,64]^T (3 terms)
            const uint32_t aH = sb + (uint32_t)(eb + O_EHI
                              + (mt * 16 + (lane & 15)) * 144 + ((lane >> 4) * 16));
            const uint32_t aL = aH + (O_ELO - O_EHI);
            const uint32_t bH = sb + (uint32_t)(eb + O_BHI
                              + (nh * 88 + brow) * 144 + ((lane & 8) << 1));
            const uint32_t bL = bH + (O_BLO - O_BHI);
            const uint32_t tH = sb + (uint32_t)(eb + O_BHI
                              + (nh * 88 + 80 + (lane & 7)) * 144 + ((lane & 8) << 1));
            const uint32_t tL = tH + (O_BLO - O_BHI);
            const int ksmax = (c == NCHK - 1) ? 3 : 4;
            #pragma unroll
            for (int ks = 0; ks < 4; ks++) {
                if (ks >= ksmax) break;
                uint32_t ah[4], al[4];
                ldsm_x4(ah, aH + ks * 32);
                ldsm_x4(al, aL + ks * 32);
                #pragma unroll
                for (int jp = 0; jp < 5; jp++) {
                    uint32_t bb = (uint32_t)(jp * 16 * 144 + ks * 32);
                    uint32_t bh[4], bl[4];
                    ldsm_x4(bh, bH + bb);
                    mma_bf16(acc + (2 * jp) * 4,     ah, bh);
                    mma_bf16(acc + (2 * jp + 1) * 4, ah, bh + 2);
                    mma_bf16(acc + (2 * jp) * 4,     al, bh);
                    mma_bf16(acc + (2 * jp + 1) * 4, al, bh + 2);
                    ldsm_x4(bl, bL + bb);
                    mma_bf16(acc + (2 * jp) * 4,     ah, bl);
                    mma_bf16(acc + (2 * jp + 1) * 4, ah, bl + 2);
                }
                // tail n8 tile (cols +80..87)
                uint32_t th[2], tl[2];
                ldsm_x2(th, tH + ks * 32);
                mma_bf16(acc + 40, ah, th);
                mma_bf16(acc + 40, al, th);
                ldsm_x2(tl, tL + ks * 32);
                mma_bf16(acc + 40, ah, tl);
            }
        } else {
            // ---- fp32 warps: exact fp32 GEMM for cols 176..255, straight from gmem
            int kp1 = 32 * c + 32; if (kp1 > 150) kp1 = 150;
            const float2* __restrict__ wt = (const float2*)g_wf32;
            #pragma unroll 1
            for (int kp = 32 * c; kp < kp1; kp++) {
                float2 w2[5];
                const float2* wp = wt + kp * 80 + cg * 5;
                #pragma unroll
                for (int j = 0; j < 5; j++) w2[j] = wp[j];
                #pragma unroll
                for (int i = 0; i < 7; i++) {
                    float2 e2 = *(const float2*)(erow[i] + 2 * kp);
                    #pragma unroll
                    for (int j = 0; j < 5; j++) {
                        facc[i][j] += e2.x * w2[j].x;
                        facc[i][j] += e2.y * w2[j].y;
                    }
                }
            }
        }

        if (c + 1 < NCHK) {
            stageE_store(ob);
            asm volatile("cp.async.wait_group 0;" ::: "memory");
        }
        __syncthreads();
    }

    // ---- dump to Dsm (aliases BUF1; last gemm used BUF0) ----
    if (isT) {
        int r0 = mt * 16 + (lane >> 2);
        int cb = (lane & 3) * 2;
        #pragma unroll
        for (int t = 0; t < 11; t++) {
            int col = nh * 88 + t * 8 + cb;
            if (r0 < SEQ) {
                Dsm[r0 * DSTRIDE + col]     = acc[t * 4 + 0];
                Dsm[r0 * DSTRIDE + col + 1] = acc[t * 4 + 1];
            }
            if (r0 + 8 < SEQ) {
                Dsm[(r0 + 8) * DSTRIDE + col]     = acc[t * 4 + 2];
                Dsm[(r0 + 8) * DSTRIDE + col + 1] = acc[t * 4 + 3];
            }
        }
    } else {
        #pragma unroll
        for (int i = 0; i < 7; i++) {
            int r = 7 * rg + i;
            if (r < SEQ) {
                #pragma unroll
                for (int j = 0; j < 5; j++)
                    Dsm[r * DSTRIDE + 176 + cg * 5 + j] = facc[i][j];
            }
        }
    }
    __syncthreads();

    // ---- top-3 per filter with on-the-fly conv (w ascending) ----
    if (tid < KN) {
        const int n = tid;
        const float gg = g_gate[n], bb = g_bias[n];
        float v1 = -1e30f, v2 = -1e30f, v3 = -1e30f;
        int   i1 = 0, i2 = 0, i3 = 0;
        for (int t = 0; t < LP; t++) {
            float s = 0.f;
            #pragma unroll
            for (int w = 0; w < KW; w++) s += Dsm[(t + w) * DSTRIDE + w * KN + n];
            float v = gg * (s + bb);
            if (v > v1)      { v3 = v2; i3 = i2; v2 = v1; i2 = i1; v1 = v; i1 = t; }
            else if (v > v2) { v3 = v2; i3 = i2; v2 = v;  i2 = t; }
            else if (v > v3) { v3 = v;  i3 = t; }
        }
        float va = v1, vb = v2, vc = v3; int ia = i1, ib = i2, ic = i3;
        if (ia > ib) { float tv = va; va = vb; vb = tv; int ti = ia; ia = ib; ib = ti; }
        if (ib > ic) { float tv = vb; vb = vc; vc = tv; int ti = ib; ib = ic; ic = ti; }
        if (ia > ib) { float tv = va; va = vb; vb = tv; int ti = ia; ia = ib; ib = ti; }
        enc[n * 3 + 0] = va; enc[n * 3 + 1] = vb; enc[n * 3 + 2] = vc;
    }
    __syncthreads();

    // ---- mlp1 ----
    if (tid < MLP1) {
        float s = hid_b[tid];
        #pragma unroll 5
        for (int i = 0; i < KN * KMAX; i++) s += enc[i] * hid_w[i * MLP1 + tid];
        float m = tanhf(s);
        mlp1s[tid] = m;
        out[(size_t)b * MLP1 + tid] = m;
    }
    __syncthreads();

    // ---- score ----
    if (tid == 0) {
        float s = score_b[0];
        for (int j = 0; j < MLP1; j++) s += mlp1s[j] * score_w[j];
        out[(size_t)Btot * MLP1 + b] = tanhf(s);
    }
}

// ---------------- launch ----------------
extern "C" void kernel_launch(void* const* d_in, const int* in_sizes, int n_in,
                              void* d_out, int out_size) {
    const int*   input_q   = (const int*)  d_in[0];
    const int*   input_d   = (const int*)  d_in[1];
    const float* emb_table = (const float*)d_in[2];
    const float* conv_w    = (const float*)d_in[3];
    const float* conv_b    = (const float*)d_in[4];
    const float* gate_w    = (const float*)d_in[5];
    const float* gate_b    = (const float*)d_in[6];
    const float* hid_w     = (const float*)d_in[7];
    const float* hid_b     = (const float*)d_in[8];
    const float* score_w   = (const float*)d_in[9];
    const float* score_b   = (const float*)d_in[10];
    float* out = (float*)d_out;

    const int Btot = in_sizes[1] / SEQ;   // 2048

    cudaFuncSetAttribute(dazer_main, cudaFuncAttributeMaxDynamicSharedMemorySize, SMEM_BYTES);

    dazer_prepA<<<1, 320>>>(input_q, emb_table);
    dazer_prepB<<<150, 256>>>(conv_w, conv_b, gate_w, gate_b);
    dazer_main<<<Btot, 704, SMEM_BYTES>>>(input_d, emb_table, hid_w, hid_b,
                                          score_w, score_b, out, Btot);
}

// round 17
// speedup vs baseline: 5.6143x; 5.6143x over previous
#include <cuda_runtime.h>
#include <cuda_bf16.h>
#include <math.h>
#include <stdint.h>

// ---------------- problem constants ----------------
#define EMB    300
#define SEQ    100
#define KW     5
#define KN     50
#define KMAX   3
#define MLP1   75
#define LP     (SEQ - KW + 1)   // 96
#define KC     64               // K per chunk
#define NCHK   5                // 5*64=320 >= 300 (zero pad); last chunk 3 ks
#define BN     256              // B rows: n' = w*50+n (250 real, 6 pad)
#define MROWS  112              // trimmed M (7 m16 tiles cover 100 doc rows)

// ---------------- device scratch ----------------
__device__ float g_cv[EMB];
__device__ float g_gate[KN];
__device__ float g_bias[KN];
// prefolded bf16-split B: [c][hi|lo][n' 0..255][k 0..63]
__device__ __align__(16) unsigned short g_bimg[NCHK * 2 * BN * KC];

// ---------------- helpers ----------------
__device__ __forceinline__ unsigned short f2bf(float x) {   // RN-even fp32->bf16
    unsigned u = __float_as_uint(x);
    return (unsigned short)((u + 0x7FFFu + ((u >> 16) & 1u)) >> 16);
}
__device__ __forceinline__ float bf2f(unsigned short h) {
    return __uint_as_float(((unsigned)h) << 16);
}
__device__ __forceinline__ uint32_t smem_u32(const void* p) {
    uint32_t a;
    asm("{ .reg .u64 t; cvta.to.shared.u64 t, %1; cvt.u32.u64 %0, t; }" : "=r"(a) : "l"(p));
    return a;
}
__device__ __forceinline__ void ldsm_x4(uint32_t* r, uint32_t addr) {
    asm volatile("ldmatrix.sync.aligned.m8n8.x4.shared.b16 {%0,%1,%2,%3}, [%4];"
                 : "=r"(r[0]), "=r"(r[1]), "=r"(r[2]), "=r"(r[3]) : "r"(addr));
}
__device__ __forceinline__ void mma_bf16(float* d, const uint32_t* a, const uint32_t* b) {
    asm volatile("mma.sync.aligned.m16n8k16.row.col.f32.bf16.bf16.f32 "
                 "{%0,%1,%2,%3}, {%4,%5,%6,%7}, {%8,%9}, {%0,%1,%2,%3};"
                 : "+f"(d[0]), "+f"(d[1]), "+f"(d[2]), "+f"(d[3])
                 : "r"(a[0]), "r"(a[1]), "r"(a[2]), "r"(a[3]), "r"(b[0]), "r"(b[1]));
}

// ---------------- prepA: class vector ----------------
__global__ void dazer_prepA(const int* __restrict__ q, const float* __restrict__ emb) {
    int t = threadIdx.x;
    if (t < EMB) {
        float s = 0.f;
        #pragma unroll
        for (int k = 0; k < 5; k++) s += emb[(size_t)q[k] * EMB + t];
        g_cv[t] = s * 0.2f;
    }
}

// ---------------- prepB: gate+bias (blk 0..49) and B fold (blk 50..149) ----
__global__ void dazer_prepB(const float* __restrict__ conv_w,
                            const float* __restrict__ conv_b,
                            const float* __restrict__ gate_w,
                            const float* __restrict__ gate_b) {
    __shared__ float red[256];
    __shared__ float cvs[EMB];
    const int tid = threadIdx.x;
    const int bid = blockIdx.x;

    for (int e = tid; e < EMB; e += 256) cvs[e] = g_cv[e];
    __syncthreads();

    if (bid < KN) {
        const int n = bid;
        float s = 0.f;
        for (int e = tid; e < EMB; e += 256) s += cvs[e] * gate_w[e * KN + n];
        red[tid] = s; __syncthreads();
        for (int o = 128; o; o >>= 1) { if (tid < o) red[tid] += red[tid + o]; __syncthreads(); }
        if (tid == 0) g_gate[n] = 1.f / (1.f + expf(-(red[0] + gate_b[n])));
        __syncthreads();
        float bs = 0.f;
        for (int idx = tid; idx < KW * EMB; idx += 256) {
            int w = idx / EMB, e = idx - w * EMB;
            bs += cvs[e] * conv_w[(w * (3 * EMB) + 2 * EMB + e) * KN + n];
        }
        red[tid] = bs; __syncthreads();
        for (int o = 128; o; o >>= 1) { if (tid < o) red[tid] += red[tid + o]; __syncthreads(); }
        if (tid == 0) g_bias[n] = red[0] + conv_b[n];
    } else {
        // fold Weff = W1 + cv[e]*W2 - W3 -> bf16 hi/lo, row n' = w*50+n
        const int total = NCHK * BN * KC;   // 81920
        for (int idx = (bid - KN) * 256 + tid; idx < total; idx += 100 * 256) {
            int k = idx & 63;
            int r = (idx >> 6) & (BN - 1);
            int c = idx >> 14;
            float v = 0.f;
            if (r < KW * KN) {
                int w = r / KN, n = r - w * KN;
                int e = c * KC + k;
                if (e < EMB) {
                    int base = w * (3 * EMB);
                    v = conv_w[(base + e) * KN + n]
                      + cvs[e] * conv_w[(base + EMB + e) * KN + n]
                      -          conv_w[(base + 2 * EMB + e) * KN + n];
                }
            }
            unsigned short hi = f2bf(v);
            unsigned short lo = f2bf(v - bf2f(hi));
            g_bimg[((c * 2 + 0) * BN + r) * KC + k] = hi;
            g_bimg[((c * 2 + 1) * BN + r) * KC + k] = lo;
        }
    }
}

// ---------------- main kernel: 1 doc/CTA, 448 thr (14 warps), double-buffered
#define O_EHI  0
#define O_ELO  16128                     // 112*144
#define O_BHI  32256
#define O_BLO  69120                     // + 256*144
#define BUFSZ  105984                    // + 256*144
#define BUF0   2048
#define BUF1   (BUF0 + BUFSZ)            // 108032
#define DSM_OFF BUF1                     // Dsm aliases BUF1 (last gemm uses BUF0)
#define DSTRIDE 264
#define CONV_OFF BUF0                    // convs aliases BUF0 (dead after dump)
#define SMEM_BYTES (BUF1 + BUFSZ)        // 214016

__global__ __launch_bounds__(448, 1)
void dazer_main(const int* __restrict__ input_d,
                const float* __restrict__ emb,
                const float* __restrict__ hid_w,
                const float* __restrict__ hid_b,
                const float* __restrict__ score_w,
                const float* __restrict__ score_b,
                float* __restrict__ out, int Btot) {
    extern __shared__ char smc[];
    int*   docids = (int*)smc;                    // [104]
    float* enc    = (float*)(smc + 448);          // [152]
    float* mlp1s  = (float*)(smc + 1088);         // [76]
    float* Dsm    = (float*)(smc + DSM_OFF);      // [100][264]
    float* convs  = (float*)(smc + CONV_OFF);     // [96*50], aliases BUF0

    const int tid  = threadIdx.x;
    const int lane = tid & 31;
    const int wid  = tid >> 5;        // 0..13
    const int mt   = wid >> 1;        // 0..6
    const int nh   = wid & 1;         // 0..1
    const int b    = blockIdx.x;

    if (tid < SEQ) docids[tid] = input_d[b * SEQ + tid];
    __syncthreads();

    const uint32_t sb = smem_u32(smc);
    const uint32_t brow = (uint32_t)((lane & 7) + ((lane & 16) >> 1));

    // ---- staging lambdas ----
    float2 ev[8];                                  // E values in flight
    auto stageE_load = [&](int c) {
        #pragma unroll
        for (int i = 0; i < 8; i++) {
            int idx = i * 448 + tid;               // 3584 = 112 rows * 32 kp
            float2 v = make_float2(0.f, 0.f);
            if (idx < MROWS * 32) {
                int row = idx >> 5, kp = idx & 31;
                int e0  = c * KC + kp * 2;
                if (row < SEQ) {
                    const float* er = emb + (size_t)docids[row] * EMB;
                    if (e0 < EMB)     v.x = er[e0];
                    if (e0 + 1 < EMB) v.y = er[e0 + 1];
                }
            }
            ev[i] = v;
        }
    };
    auto stageE_store = [&](int base) {
        #pragma unroll
        for (int i = 0; i < 8; i++) {
            int idx = i * 448 + tid;
            if (idx < MROWS * 32) {
                int row = idx >> 5, kp = idx & 31;
                unsigned short h0 = f2bf(ev[i].x), h1 = f2bf(ev[i].y);
                unsigned short l0 = f2bf(ev[i].x - bf2f(h0));
                unsigned short l1 = f2bf(ev[i].y - bf2f(h1));
                *(uint32_t*)(smc + base + O_EHI + row * 144 + kp * 4) =
                    (uint32_t)h0 | ((uint32_t)h1 << 16);
                *(uint32_t*)(smc + base + O_ELO + row * 144 + kp * 4) =
                    (uint32_t)l0 | ((uint32_t)l1 << 16);
            }
        }
    };
    auto stageB = [&](int c, int base) {           // async, no registers held
        const char* bsrc = (const char*)g_bimg;
        #pragma unroll
        for (int img = 0; img < 2; img++) {
            int dsto = base + (img ? O_BLO : O_BHI);
            #pragma unroll
            for (int i = 0; i < 5; i++) {          // 2048 per img / 448 thr
                int idx = i * 448 + tid;
                if (idx < BN * 8) {
                    int row = idx >> 3, u = idx & 7;
                    uint32_t dst = sb + (uint32_t)(dsto + row * 144 + u * 16);
                    const void* src = bsrc +
                        ((size_t)((c * 2 + img) * BN + row) * KC) * 2 + u * 16;
                    asm volatile("cp.async.cg.shared.global [%0], [%1], 16;"
                                 :: "r"(dst), "l"(src));
                }
            }
        }
        asm volatile("cp.async.commit_group;" ::: "memory");
    };

    // ---- prologue: chunk 0 into BUF0 ----
    stageB(0, BUF0);
    stageE_load(0);
    stageE_store(BUF0);
    asm volatile("cp.async.wait_group 0;" ::: "memory");
    __syncthreads();

    float acc[64];
    #pragma unroll
    for (int i = 0; i < 64; i++) acc[i] = 0.f;

    #pragma unroll 1
    for (int c = 0; c < NCHK; c++) {
        const int eb = (c & 1) ? BUF1 : BUF0;
        const int ob = (c & 1) ? BUF0 : BUF1;
        if (c + 1 < NCHK) {
            stageB(c + 1, ob);                     // async into other buffer
            stageE_load(c + 1);                    // LDG latency hidden by gemm
        }

        // ---- warp GEMM: D[16,128] += E[16,64] * B[128,64]^T, 3 split terms
        const uint32_t aH = sb + (uint32_t)(eb + O_EHI
                          + (mt * 16 + (lane & 15)) * 144 + ((lane >> 4) * 16));
        const uint32_t aL = aH + (O_ELO - O_EHI);
        const uint32_t bH = sb + (uint32_t)(eb + O_BHI
                          + (nh * 128 + brow) * 144 + ((lane & 8) << 1));
        const uint32_t bL = bH + (O_BLO - O_BHI);
        const int ksmax = (c == NCHK - 1) ? 3 : 4; // K-trim: e>=304 all zero
        #pragma unroll
        for (int ks = 0; ks < 4; ks++) {
            if (ks >= ksmax) break;
            uint32_t ah[4], al[4];
            ldsm_x4(ah, aH + ks * 32);
            ldsm_x4(al, aL + ks * 32);
            #pragma unroll
            for (int jp = 0; jp < 8; jp++) {
                uint32_t bb = (uint32_t)(jp * 16 * 144 + ks * 32);
                uint32_t bh[4], bl[4];
                ldsm_x4(bh, bH + bb);
                mma_bf16(acc + (2 * jp) * 4,     ah, bh);
                mma_bf16(acc + (2 * jp + 1) * 4, ah, bh + 2);
                mma_bf16(acc + (2 * jp) * 4,     al, bh);
                mma_bf16(acc + (2 * jp + 1) * 4, al, bh + 2);
                ldsm_x4(bl, bL + bb);
                mma_bf16(acc + (2 * jp) * 4,     ah, bl);
                mma_bf16(acc + (2 * jp + 1) * 4, ah, bl + 2);
            }
        }

        if (c + 1 < NCHK) {
            stageE_store(ob);
            asm volatile("cp.async.wait_group 0;" ::: "memory");
        }
        __syncthreads();
    }

    // ---- dump fragments to Dsm (aliases BUF1; last gemm used BUF0) ----
    {
        int r0 = mt * 16 + (lane >> 2);
        int cb = (lane & 3) * 2;
        #pragma unroll
        for (int j = 0; j < 16; j++) {
            int col = nh * 128 + j * 8 + cb;
            if (r0 < SEQ) {
                Dsm[r0 * DSTRIDE + col]     = acc[j * 4 + 0];
                Dsm[r0 * DSTRIDE + col + 1] = acc[j * 4 + 1];
            }
            if (r0 + 8 < SEQ) {
                Dsm[(r0 + 8) * DSTRIDE + col]     = acc[j * 4 + 2];
                Dsm[(r0 + 8) * DSTRIDE + col + 1] = acc[j * 4 + 3];
            }
        }
    }
    __syncthreads();   // Dsm complete; BUF0 staging dead -> convs may overwrite

    // ---- conv (parallel, all 448 threads): convs[t*50+n], w ascending ----
    for (int idx = tid; idx < LP * KN; idx += 448) {
        int t = idx / KN, n = idx - t * KN;
        float s = 0.f;
        #pragma unroll
        for (int w = 0; w < KW; w++) s += Dsm[(t + w) * DSTRIDE + w * KN + n];
        convs[idx] = g_gate[n] * (s + g_bias[n]);
    }
    __syncthreads();

    // ---- top-3 per filter, original order (strict > == jax top_k tie-break)
    if (tid < KN) {
        const int n = tid;
        float v1 = -1e30f, v2 = -1e30f, v3 = -1e30f;
        int   i1 = 0, i2 = 0, i3 = 0;
        for (int t = 0; t < LP; t++) {
            float v = convs[t * KN + n];
            if (v > v1)      { v3 = v2; i3 = i2; v2 = v1; i2 = i1; v1 = v; i1 = t; }
            else if (v > v2) { v3 = v2; i3 = i2; v2 = v;  i2 = t; }
            else if (v > v3) { v3 = v;  i3 = t; }
        }
        float va = v1, vb = v2, vc = v3; int ia = i1, ib = i2, ic = i3;
        if (ia > ib) { float tv = va; va = vb; vb = tv; int ti = ia; ia = ib; ib = ti; }
        if (ib > ic) { float tv = vb; vb = vc; vc = tv; int ti = ib; ib = ic; ic = ti; }
        if (ia > ib) { float tv = va; va = vb; vb = tv; int ti = ia; ia = ib; ib = ti; }
        enc[n * 3 + 0] = va; enc[n * 3 + 1] = vb; enc[n * 3 + 2] = vc;
    }
    __syncthreads();

    // ---- mlp1 = tanh(enc @ hid_w + hid_b) ----
    if (tid < MLP1) {
        float s = hid_b[tid];
        #pragma unroll 5
        for (int i = 0; i < KN * KMAX; i++) s += enc[i] * hid_w[i * MLP1 + tid];
        float m = tanhf(s);
        mlp1s[tid] = m;
        out[(size_t)b * MLP1 + tid] = m;
    }
    __syncthreads();

    // ---- score ----
    if (tid == 0) {
        float s = score_b[0];
        for (int j = 0; j < MLP1; j++) s += mlp1s[j] * score_w[j];
        out[(size_t)Btot * MLP1 + b] = tanhf(s);
    }
}

// ---------------- launch ----------------
extern "C" void kernel_launch(void* const* d_in, const int* in_sizes, int n_in,
                              void* d_out, int out_size) {
    const int*   input_q   = (const int*)  d_in[0];
    const int*   input_d   = (const int*)  d_in[1];
    const float* emb_table = (const float*)d_in[2];
    const float* conv_w    = (const float*)d_in[3];
    const float* conv_b    = (const float*)d_in[4];
    const float* gate_w    = (const float*)d_in[5];
    const float* gate_b    = (const float*)d_in[6];
    const float* hid_w     = (const float*)d_in[7];
    const float* hid_b     = (const float*)d_in[8];
    const float* score_w   = (const float*)d_in[9];
    const float* score_b   = (const float*)d_in[10];
    float* out = (float*)d_out;

    const int Btot = in_sizes[1] / SEQ;   // 2048

    cudaFuncSetAttribute(dazer_main, cudaFuncAttributeMaxDynamicSharedMemorySize, SMEM_BYTES);

    dazer_prepA<<<1, 320>>>(input_q, emb_table);
    dazer_prepB<<<150, 256>>>(conv_w, conv_b, gate_w, gate_b);
    dazer_main<<<Btot, 448, SMEM_BYTES>>>(input_d, emb_table, hid_w, hid_b,
                                          score_w, score_b, out, Btot);
}